// round 14
// baseline (speedup 1.0000x reference)
#include <cuda_runtime.h>
#include <cuda_bf16.h>
#include <math.h>
#include <stdint.h>

#define Bq 4
#define NNODE 4096
#define HH 128
#define ITERS 8
#define EPS 1e-5f
#define MROWS (Bq * NNODE)   // 16384
#define KSPLIT 2
#define KSLICE (NNODE / KSPLIT)   // 2048

// smem paddings (bf16 elems per row)
#define XP 40    // 32 + 8
#define MP 136   // 128 + 8

// ---------------- scratch (device globals; no allocs allowed) ----------------
__device__ float g_init0[Bq * HH];
__device__ float g_c[(size_t)MROWS * HH];
__device__ float g_vote[MROWS];
__device__ float g_msgp[(size_t)KSPLIT * MROWS * HH];        // split-K partials (16 MB)
__device__ __nv_bfloat16 g_xb[(size_t)Bq * NNODE * NNODE];   // 128 MB
__device__ __nv_bfloat16 g_amh[(size_t)MROWS * 256];         // [msg | h]
__device__ __nv_bfloat16 g_hb[(size_t)MROWS * HH];           // h_new (gates epilogue out)
__device__ __nv_bfloat16 g_eb[(size_t)MROWS * HH];           // embed
__device__ __nv_bfloat16 g_mb[(size_t)MROWS * HH];           // m (msg-MLP out)
__device__ __nv_bfloat16 g_t2b[(size_t)MROWS * HH];          // vote hidden
// transposed bf16 weights: wt[k][n]
__device__ __nv_bfloat16 g_wm1[HH * HH], g_wm2[HH * HH], g_wm3[HH * HH];
__device__ __nv_bfloat16 g_wv1[HH * HH], g_wv2[HH * HH];
__device__ __nv_bfloat16 g_wcat[256 * 512];                  // gate-interleaved [Wih;Whh]^T

// ---------------- helpers ----------------
__device__ __forceinline__ float sigf(float x) { return 1.f / (1.f + expf(-x)); }
__device__ __forceinline__ uint32_t s2u(const void* p) {
    return (uint32_t)__cvta_generic_to_shared(p);
}
__device__ __forceinline__ void cpa16(void* dst, const void* src) {
    asm volatile("cp.async.cg.shared.global [%0], [%1], 16;\n" :: "r"(s2u(dst)), "l"(src));
}
#define CP_COMMIT() asm volatile("cp.async.commit_group;\n" ::: "memory")
#define CP_WAIT0()  asm volatile("cp.async.wait_group 0;\n" ::: "memory")
#define CP_WAIT1()  asm volatile("cp.async.wait_group 1;\n" ::: "memory")

__device__ __forceinline__ float blockSum128(float v) {
    __shared__ float sw[4];
    #pragma unroll
    for (int o = 16; o > 0; o >>= 1) v += __shfl_xor_sync(0xffffffffu, v, o);
    __syncthreads();
    if ((threadIdx.x & 31) == 0) sw[threadIdx.x >> 5] = v;
    __syncthreads();
    return sw[0] + sw[1] + sw[2] + sw[3];
}

__device__ __forceinline__ void ldmA(uint32_t* r, uint32_t addr) {
    asm volatile("ldmatrix.sync.aligned.m8n8.x4.shared.b16 {%0,%1,%2,%3}, [%4];\n"
                 : "=r"(r[0]), "=r"(r[1]), "=r"(r[2]), "=r"(r[3]) : "r"(addr));
}
__device__ __forceinline__ void ldmBT(uint32_t* r, uint32_t addr) {
    asm volatile("ldmatrix.sync.aligned.m8n8.x2.trans.shared.b16 {%0,%1}, [%2];\n"
                 : "=r"(r[0]), "=r"(r[1]) : "r"(addr));
}
__device__ __forceinline__ void mma16816(float* d, const uint32_t* a, const uint32_t* b) {
    asm volatile(
        "mma.sync.aligned.m16n8k16.row.col.f32.bf16.bf16.f32 "
        "{%0,%1,%2,%3}, {%4,%5,%6,%7}, {%8,%9}, {%0,%1,%2,%3};\n"
        : "+f"(d[0]), "+f"(d[1]), "+f"(d[2]), "+f"(d[3])
        : "r"(a[0]), "r"(a[1]), "r"(a[2]), "r"(a[3]), "r"(b[0]), "r"(b[1]));
}
__device__ __forceinline__ uint32_t packbf2(float x, float y) {
    __nv_bfloat162 p = __floats2bfloat162_rn(x, y);
    return *(uint32_t*)&p;
}

// ---------------- conversions (once per launch) ----------------
__global__ void k_cvt_x(const float* __restrict__ X, __nv_bfloat16* __restrict__ Xb) {
    size_t i = ((size_t)blockIdx.x * blockDim.x + threadIdx.x) * 4;
    float4 v = *(const float4*)&X[i];
    uint2 u;
    u.x = packbf2(v.x, v.y);
    u.y = packbf2(v.z, v.w);
    *(uint2*)&Xb[i] = u;
}
// all weight transposes in ONE kernel. jobs 0-4: HxH -> [k][n];
// jobs 5,6: wih/whh -> wcat GATE-INTERLEAVED: col p = 4*feat + gate
__global__ void k_cvtw(const float* s0, const float* s1, const float* s2,
                       const float* s3, const float* s4,
                       const float* wih, const float* whh,
                       __nv_bfloat16* d0, __nv_bfloat16* d1, __nv_bfloat16* d2,
                       __nv_bfloat16* d3, __nv_bfloat16* d4,
                       __nv_bfloat16* dcat) {
    int idx = blockIdx.x * 256 + threadIdx.x;
    int job = blockIdx.y;
    if (job < 5) {
        if (idx >= HH * HH) return;
        const float* s; __nv_bfloat16* d;
        switch (job) {
            case 0: s = s0; d = d0; break;
            case 1: s = s1; d = d1; break;
            case 2: s = s2; d = d2; break;
            case 3: s = s3; d = d3; break;
            default: s = s4; d = d4; break;
        }
        int n = idx >> 7, k = idx & 127;
        d[k * HH + n] = __float2bfloat16(s[idx]);
    } else {
        if (idx >= 512 * HH) return;
        const float* s = (job == 5) ? wih : whh;
        int koff = (job == 5) ? 0 : 128;
        int n = idx >> 7, k = idx & 127;          // n = gate*128 + feat
        int p = ((n & 127) << 2) | (n >> 7);      // 4*feat + gate
        dcat[(size_t)(k + koff) * 512 + p] = __float2bfloat16(s[idx]);
    }
}

// ---------------- tiny init MLP ----------------
__global__ void k_init(const float* __restrict__ kv, const float* __restrict__ nv,
                       const float* __restrict__ w1, const float* __restrict__ b1,
                       const float* __restrict__ w2, const float* __restrict__ b2,
                       const float* __restrict__ w3, const float* __restrict__ b3,
                       float* __restrict__ init0) {
    int b = blockIdx.x, j = threadIdx.x;
    __shared__ float s1[HH], s2[HH];
    float kk = kv[b], nn = nv[b];
    float v = fmaxf(w1[j * 2 + 0] * kk + w1[j * 2 + 1] * nn + b1[j], 0.f);
    s1[j] = v;
    __syncthreads();
    float acc = b2[j];
    #pragma unroll 8
    for (int t = 0; t < HH; t++) acc += w2[j * HH + t] * s1[t];
    s2[j] = fmaxf(acc, 0.f);
    __syncthreads();
    acc = b3[j];
    #pragma unroll 8
    for (int t = 0; t < HH; t++) acc += w3[j * HH + t] * s2[t];
    init0[b * HH + j] = acc;
}

// ---------------- broadcast: h(bf16)->amh, c=0, embed(bf16) ----------------
__global__ void k_bcast(const float* __restrict__ init0,
                        const float* __restrict__ lng, const float* __restrict__ lnb,
                        __nv_bfloat16* __restrict__ amh, float* __restrict__ c,
                        __nv_bfloat16* __restrict__ eb) {
    int b = blockIdx.y, i = blockIdx.x, j = threadIdx.x;
    float v = init0[b * HH + j];
    float mu = blockSum128(v) * (1.f / HH);
    float xc = v - mu;
    float var = blockSum128(xc * xc) * (1.f / HH);
    float e = xc * rsqrtf(var + EPS) * lng[j] + lnb[j];
    size_t row = (size_t)b * NNODE + i;
    amh[row * 256 + 128 + j] = __float2bfloat16(v);
    c[row * HH + j] = 0.f;
    eb[row * HH + j] = __float2bfloat16(e);
}

// ---------------- fused NL-layer MLP (bf16 mma), 128 rows/block ----------------
template <int NL, bool LAST_RELU>
__global__ void __launch_bounds__(256) k_mlpN(const __nv_bfloat16* __restrict__ in,
                                              const __nv_bfloat16* __restrict__ w0,
                                              const __nv_bfloat16* __restrict__ w1,
                                              const __nv_bfloat16* __restrict__ w2,
                                              const float* __restrict__ b0,
                                              const float* __restrict__ b1,
                                              const float* __restrict__ b2,
                                              __nv_bfloat16* __restrict__ out) {
    int m0 = blockIdx.x * 128;
    __shared__ __align__(16) __nv_bfloat16 Ab[128 * MP];
    __shared__ __align__(16) __nv_bfloat16 Wb[128 * MP];
    int tid = threadIdx.x;
    int lane = tid & 31, wid = tid >> 5;
    int warp_m = wid >> 2, warp_n = wid & 3;

    #pragma unroll
    for (int r = 0; r < 8; r++) {
        int idx = tid + r * 256;
        int row = idx >> 4, cs = idx & 15;
        cpa16(&Ab[row * MP + cs * 8], &in[(size_t)(m0 + row) * HH + cs * 8]);
    }
    CP_COMMIT();

    #pragma unroll
    for (int l = 0; l < NL; l++) {
        const __nv_bfloat16* wt = (l == 0) ? w0 : (l == 1) ? w1 : w2;
        const float* bias = (l == 0) ? b0 : (l == 1) ? b1 : b2;
        bool relu = (l < NL - 1) || LAST_RELU;
        #pragma unroll
        for (int r = 0; r < 8; r++) {
            int idx = tid + r * 256;
            int row = idx >> 4, cs = idx & 15;
            cpa16(&Wb[row * MP + cs * 8], &wt[(size_t)row * HH + cs * 8]);
        }
        CP_COMMIT();
        CP_WAIT0();
        __syncthreads();

        float acc[4][4][4];
        #pragma unroll
        for (int mi = 0; mi < 4; mi++)
            #pragma unroll
            for (int ni = 0; ni < 4; ni++)
                #pragma unroll
                for (int e = 0; e < 4; e++) acc[mi][ni][e] = 0.f;

        #pragma unroll
        for (int ks = 0; ks < 8; ks++) {
            int kk = ks * 16;
            uint32_t a[4][4], bb[4][2];
            #pragma unroll
            for (int mi = 0; mi < 4; mi++)
                ldmA(a[mi], s2u(&Ab[(warp_m * 64 + mi * 16 + (lane & 15)) * MP
                                    + kk + ((lane >> 4) << 3)]));
            #pragma unroll
            for (int ni = 0; ni < 4; ni++)
                ldmBT(bb[ni], s2u(&Wb[(kk + (lane & 15)) * MP + warp_n * 32 + ni * 8]));
            #pragma unroll
            for (int mi = 0; mi < 4; mi++)
                #pragma unroll
                for (int ni = 0; ni < 4; ni++) mma16816(acc[mi][ni], a[mi], bb[ni]);
        }
        __syncthreads();

        #pragma unroll
        for (int mi = 0; mi < 4; mi++)
            #pragma unroll
            for (int ni = 0; ni < 4; ni++) {
                int rl = warp_m * 64 + mi * 16 + (lane >> 2);
                int col = warp_n * 32 + ni * 8 + ((lane & 3) << 1);
                float bv0 = bias[col], bv1 = bias[col + 1];
                float v0 = acc[mi][ni][0] + bv0, v1 = acc[mi][ni][1] + bv1;
                float v2 = acc[mi][ni][2] + bv0, v3 = acc[mi][ni][3] + bv1;
                if (relu) {
                    v0 = fmaxf(v0, 0.f); v1 = fmaxf(v1, 0.f);
                    v2 = fmaxf(v2, 0.f); v3 = fmaxf(v3, 0.f);
                }
                uint32_t p0 = packbf2(v0, v1), p1 = packbf2(v2, v3);
                if (l < NL - 1) {
                    *(uint32_t*)&Ab[rl * MP + col] = p0;
                    *(uint32_t*)&Ab[(rl + 8) * MP + col] = p1;
                } else {
                    *(uint32_t*)&out[(size_t)(m0 + rl) * HH + col] = p0;
                    *(uint32_t*)&out[(size_t)(m0 + rl + 8) * HH + col] = p1;
                }
            }
        __syncthreads();
    }
}

// ---------------- tensor-core aggregation, split-K=2 ----------------
__device__ __forceinline__ void aggr_load(int tid, const __nv_bfloat16* __restrict__ A,
                                          const __nv_bfloat16* __restrict__ Bm,
                                          int m0, int k0,
                                          __nv_bfloat16* xs, __nv_bfloat16* ms) {
    #pragma unroll
    for (int r = 0; r < 2; r++) {
        int seg = tid + r * 256;
        int row = seg >> 2, cs = seg & 3;
        cpa16(&xs[row * XP + cs * 8], &A[(size_t)(m0 + row) * NNODE + k0 + cs * 8]);
    }
    #pragma unroll
    for (int r = 0; r < 2; r++) {
        int seg = tid + r * 256;
        int row = seg >> 4, cs = seg & 15;
        cpa16(&ms[row * MP + cs * 8], &Bm[(size_t)(k0 + row) * HH + cs * 8]);
    }
}

__global__ void __launch_bounds__(256) k_aggr_mma(const __nv_bfloat16* __restrict__ Xb,
                                                  const __nv_bfloat16* __restrict__ Mb,
                                                  float* __restrict__ MSGP) {
    int b = blockIdx.y;
    int ks = blockIdx.z;
    const __nv_bfloat16* A  = Xb + (size_t)b * NNODE * NNODE;
    const __nv_bfloat16* Bm = Mb + (size_t)b * NNODE * HH;
    float* C = MSGP + ((size_t)ks * MROWS + (size_t)b * NNODE) * HH;
    int m0 = blockIdx.x * 128;
    int kbase = ks * KSLICE;

    __shared__ __align__(16) __nv_bfloat16 Xs[3][128 * XP];
    __shared__ __align__(16) __nv_bfloat16 Ms[3][32 * MP];

    int tid = threadIdx.x;
    int lane = tid & 31, wid = tid >> 5;
    int warp_m = wid >> 2, warp_n = wid & 3;

    float acc[4][4][4];
    #pragma unroll
    for (int mi = 0; mi < 4; mi++)
        #pragma unroll
        for (int ni = 0; ni < 4; ni++)
            #pragma unroll
            for (int e = 0; e < 4; e++) acc[mi][ni][e] = 0.f;

    aggr_load(tid, A, Bm, m0, kbase, Xs[0], Ms[0]);
    CP_COMMIT();
    aggr_load(tid, A, Bm, m0, kbase + 32, Xs[1], Ms[1]);
    CP_COMMIT();

    const int NC = KSLICE / 32;   // 64 chunks
    for (int kc = 0; kc < NC; kc++) {
        int cur = kc % 3;
        if (kc < NC - 1) { CP_WAIT1(); } else { CP_WAIT0(); }
        __syncthreads();
        if (kc + 2 < NC) {
            aggr_load(tid, A, Bm, m0, kbase + (kc + 2) * 32, Xs[(kc + 2) % 3], Ms[(kc + 2) % 3]);
            CP_COMMIT();
        }
        #pragma unroll
        for (int ksub = 0; ksub < 2; ksub++) {
            int kk = ksub * 16;
            uint32_t a[4][4], bb[4][2];
            #pragma unroll
            for (int mi = 0; mi < 4; mi++)
                ldmA(a[mi], s2u(&Xs[cur][(warp_m * 64 + mi * 16 + (lane & 15)) * XP
                                         + kk + ((lane >> 4) << 3)]));
            #pragma unroll
            for (int ni = 0; ni < 4; ni++)
                ldmBT(bb[ni], s2u(&Ms[cur][(kk + (lane & 15)) * MP + warp_n * 32 + ni * 8]));
            #pragma unroll
            for (int mi = 0; mi < 4; mi++)
                #pragma unroll
                for (int ni = 0; ni < 4; ni++) mma16816(acc[mi][ni], a[mi], bb[ni]);
        }
    }

    #pragma unroll
    for (int mi = 0; mi < 4; mi++)
        #pragma unroll
        for (int ni = 0; ni < 4; ni++) {
            int row = m0 + warp_m * 64 + mi * 16 + (lane >> 2);
            int col = warp_n * 32 + ni * 8 + ((lane & 3) << 1);
            float2 v0 = {acc[mi][ni][0], acc[mi][ni][1]};
            float2 v1 = {acc[mi][ni][2], acc[mi][ni][3]};
            *(float2*)&C[(size_t)row * HH + col] = v0;
            *(float2*)&C[(size_t)(row + 8) * HH + col] = v1;
        }
}

// ---------------- reduce split-K partials -> bf16 msg in amh ----------------
__global__ void k_reduce_msg(const float* __restrict__ MSGP,
                             __nv_bfloat16* __restrict__ AMH) {
    size_t i = ((size_t)blockIdx.x * 256 + threadIdx.x) * 4;
    float4 a = *(const float4*)&MSGP[i];
    float4 bphalf = *(const float4*)&MSGP[(size_t)MROWS * HH + i];
    size_t row = i >> 7;
    int col = (int)(i & 127);
    uint2 u;
    u.x = packbf2(a.x + bphalf.x, a.y + bphalf.y);
    u.y = packbf2(a.z + bphalf.z, a.w + bphalf.w);
    *(uint2*)&AMH[row * 256 + col] = u;
}

// ---------------- gates GEMM + fused LSTM cell ----------------
// A = amh[M,256] ([msg|h]); W = gate-interleaved wcat[256,512] (col p = 4f+g)
// epilogue: lane pairs exchange (i,f)/(g,o) via shfl; even lanes write c, h_new
__global__ void __launch_bounds__(256) k_gates_lstm(const __nv_bfloat16* __restrict__ AMH,
                                                    const __nv_bfloat16* __restrict__ Wc,
                                                    const float* __restrict__ bih,
                                                    const float* __restrict__ bhh,
                                                    float* __restrict__ c,
                                                    __nv_bfloat16* __restrict__ hnew) {
    int m0 = blockIdx.x * 128;
    int n0 = blockIdx.y * 128;

    __shared__ __align__(16) __nv_bfloat16 Xs[3][128 * XP];
    __shared__ __align__(16) __nv_bfloat16 Ms[3][32 * MP];

    int tid = threadIdx.x;
    int lane = tid & 31, wid = tid >> 5;
    int warp_m = wid >> 2, warp_n = wid & 3;

    float acc[4][4][4];
    #pragma unroll
    for (int mi = 0; mi < 4; mi++)
        #pragma unroll
        for (int ni = 0; ni < 4; ni++)
            #pragma unroll
            for (int e = 0; e < 4; e++) acc[mi][ni][e] = 0.f;

    auto load = [&](int k0, __nv_bfloat16* xs, __nv_bfloat16* ms) {
        #pragma unroll
        for (int r = 0; r < 2; r++) {
            int seg = tid + r * 256;
            int row = seg >> 2, cs = seg & 3;
            cpa16(&xs[row * XP + cs * 8], &AMH[(size_t)(m0 + row) * 256 + k0 + cs * 8]);
        }
        #pragma unroll
        for (int r = 0; r < 2; r++) {
            int seg = tid + r * 256;
            int row = seg >> 4, cs = seg & 15;
            cpa16(&ms[row * MP + cs * 8], &Wc[(size_t)(k0 + row) * 512 + n0 + cs * 8]);
        }
    };

    load(0, Xs[0], Ms[0]);
    CP_COMMIT();
    load(32, Xs[1], Ms[1]);
    CP_COMMIT();

    const int NC = 256 / 32;
    for (int kc = 0; kc < NC; kc++) {
        int cur = kc % 3;
        if (kc < NC - 1) { CP_WAIT1(); } else { CP_WAIT0(); }
        __syncthreads();
        if (kc + 2 < NC) {
            load((kc + 2) * 32, Xs[(kc + 2) % 3], Ms[(kc + 2) % 3]);
            CP_COMMIT();
        }
        #pragma unroll
        for (int ks = 0; ks < 2; ks++) {
            int kk = ks * 16;
            uint32_t a[4][4], bb[4][2];
            #pragma unroll
            for (int mi = 0; mi < 4; mi++)
                ldmA(a[mi], s2u(&Xs[cur][(warp_m * 64 + mi * 16 + (lane & 15)) * XP
                                         + kk + ((lane >> 4) << 3)]));
            #pragma unroll
            for (int ni = 0; ni < 4; ni++)
                ldmBT(bb[ni], s2u(&Ms[cur][(kk + (lane & 15)) * MP + warp_n * 32 + ni * 8]));
            #pragma unroll
            for (int mi = 0; mi < 4; mi++)
                #pragma unroll
                for (int ni = 0; ni < 4; ni++) mma16816(acc[mi][ni], a[mi], bb[ni]);
        }
    }

    // epilogue: interleaved cols; cg even. t=lane&3: t even -> (i,f); t odd -> (g,o)
    #pragma unroll
    for (int mi = 0; mi < 4; mi++)
        #pragma unroll
        for (int ni = 0; ni < 4; ni++) {
            int row = m0 + warp_m * 64 + mi * 16 + (lane >> 2);
            int cg = n0 + warp_n * 32 + ni * 8 + ((lane & 3) << 1);
            int gA = cg & 3, fA = cg >> 2;
            int gB = (cg + 1) & 3, fB = (cg + 1) >> 2;
            float b0 = bih[gA * 128 + fA] + bhh[gA * 128 + fA];
            float b1 = bih[gB * 128 + fB] + bhh[gB * 128 + fB];
            float a0 = acc[mi][ni][0] + b0, a1 = acc[mi][ni][1] + b1;
            float a2 = acc[mi][ni][2] + b0, a3 = acc[mi][ni][3] + b1;
            float o0 = __shfl_xor_sync(0xffffffffu, a0, 1);
            float o1 = __shfl_xor_sync(0xffffffffu, a1, 1);
            float o2 = __shfl_xor_sync(0xffffffffu, a2, 1);
            float o3 = __shfl_xor_sync(0xffffffffu, a3, 1);
            if (!(lane & 1)) {
                // this lane holds (i,f) = (a0,a1); partner supplied (g,o) = (o0,o1)
                int feat = cg >> 2;
                size_t coff = (size_t)row * HH + feat;
                float cc = sigf(a1) * c[coff] + sigf(a0) * tanhf(o0);
                float hh = sigf(o1) * tanhf(cc);
                c[coff] = cc;
                hnew[(size_t)row * HH + feat] = __float2bfloat16(hh);
                size_t coff8 = coff + (size_t)8 * HH;
                float cc8 = sigf(a3) * c[coff8] + sigf(a2) * tanhf(o2);
                float hh8 = sigf(o3) * tanhf(cc8);
                c[coff8] = cc8;
                hnew[(size_t)(row + 8) * HH + feat] = __float2bfloat16(hh8);
            }
        }
}

// ---------------- h_new -> amh h-slot + LayerNorm -> embed ----------------
__global__ void k_hln(const __nv_bfloat16* __restrict__ hnew,
                      __nv_bfloat16* __restrict__ amh, __nv_bfloat16* __restrict__ eb,
                      const float* __restrict__ lng, const float* __restrict__ lnb) {
    size_t row = blockIdx.x;
    int j = threadIdx.x;
    __nv_bfloat16 hb = hnew[row * HH + j];
    float hh = __bfloat162float(hb);
    amh[row * 256 + 128 + j] = hb;
    float mu = blockSum128(hh) * (1.f / HH);
    float xc = hh - mu;
    float var = blockSum128(xc * xc) * (1.f / HH);
    eb[row * HH + j] = __float2bfloat16(xc * rsqrtf(var + EPS) * lng[j] + lnb[j]);
}

// ---------------- vote dot + mask ----------------
__global__ void k_vote(const __nv_bfloat16* __restrict__ t2, const float* __restrict__ w3,
                       const float* __restrict__ b3, const float* __restrict__ mask,
                       float* __restrict__ vote) {
    size_t row = blockIdx.x;
    int j = threadIdx.x;
    float v = __bfloat162float(t2[row * HH + j]) * w3[j];
    float s = blockSum128(v);
    if (j == 0) vote[row] = (s + b3[0]) * mask[row];
}

// ---------------- final masked sum + sigmoid ----------------
__global__ void k_final(const float* __restrict__ vote, float* __restrict__ out) {
    __shared__ float sw[8];
    int b = blockIdx.x;
    float s = 0.f;
    for (int i = threadIdx.x; i < NNODE; i += blockDim.x) s += vote[(size_t)b * NNODE + i];
    #pragma unroll
    for (int o = 16; o > 0; o >>= 1) s += __shfl_xor_sync(0xffffffffu, s, o);
    if ((threadIdx.x & 31) == 0) sw[threadIdx.x >> 5] = s;
    __syncthreads();
    if (threadIdx.x == 0) {
        float t = 0.f;
        #pragma unroll
        for (int w = 0; w < 8; w++) t += sw[w];
        out[b] = 1.f / (1.f + expf(-t));
    }
}

// ---------------- launch ----------------
extern "C" void kernel_launch(void* const* d_in, const int* in_sizes, int n_in,
                              void* d_out, int out_size) {
    const float* x       = (const float*)d_in[0];
    const float* kv      = (const float*)d_in[1];
    const float* nv      = (const float*)d_in[2];
    const float* mask    = (const float*)d_in[3];
    const float* init_w1 = (const float*)d_in[4];
    const float* init_b1 = (const float*)d_in[5];
    const float* init_w2 = (const float*)d_in[6];
    const float* init_b2 = (const float*)d_in[7];
    const float* init_w3 = (const float*)d_in[8];
    const float* init_b3 = (const float*)d_in[9];
    const float* msg_w1  = (const float*)d_in[10];
    const float* msg_b1  = (const float*)d_in[11];
    const float* msg_w2  = (const float*)d_in[12];
    const float* msg_b2  = (const float*)d_in[13];
    const float* msg_w3  = (const float*)d_in[14];
    const float* msg_b3  = (const float*)d_in[15];
    const float* lstm_wih = (const float*)d_in[16];
    const float* lstm_whh = (const float*)d_in[17];
    const float* lstm_bih = (const float*)d_in[18];
    const float* lstm_bhh = (const float*)d_in[19];
    const float* ln_g    = (const float*)d_in[20];
    const float* ln_b    = (const float*)d_in[21];
    const float* vote_w1 = (const float*)d_in[22];
    const float* vote_b1 = (const float*)d_in[23];
    const float* vote_w2 = (const float*)d_in[24];
    const float* vote_b2 = (const float*)d_in[25];
    const float* vote_w3 = (const float*)d_in[26];
    const float* vote_b3 = (const float*)d_in[27];
    float* out = (float*)d_out;

    float *p_init0, *p_c, *p_vote, *p_msgp;
    __nv_bfloat16 *p_xb, *p_amh, *p_hb, *p_eb, *p_mb, *p_t2b;
    __nv_bfloat16 *p_wm1, *p_wm2, *p_wm3, *p_wv1, *p_wv2, *p_wcat;
    cudaGetSymbolAddress((void**)&p_init0, g_init0);
    cudaGetSymbolAddress((void**)&p_c, g_c);
    cudaGetSymbolAddress((void**)&p_vote, g_vote);
    cudaGetSymbolAddress((void**)&p_msgp, g_msgp);
    cudaGetSymbolAddress((void**)&p_xb, g_xb);
    cudaGetSymbolAddress((void**)&p_amh, g_amh);
    cudaGetSymbolAddress((void**)&p_hb, g_hb);
    cudaGetSymbolAddress((void**)&p_eb, g_eb);
    cudaGetSymbolAddress((void**)&p_mb, g_mb);
    cudaGetSymbolAddress((void**)&p_t2b, g_t2b);
    cudaGetSymbolAddress((void**)&p_wm1, g_wm1);
    cudaGetSymbolAddress((void**)&p_wm2, g_wm2);
    cudaGetSymbolAddress((void**)&p_wm3, g_wm3);
    cudaGetSymbolAddress((void**)&p_wv1, g_wv1);
    cudaGetSymbolAddress((void**)&p_wv2, g_wv2);
    cudaGetSymbolAddress((void**)&p_wcat, g_wcat);

    k_cvt_x<<<(size_t)Bq * NNODE * NNODE / 4 / 256, 256>>>(x, p_xb);
    k_cvtw<<<dim3(256, 7), 256>>>(msg_w1, msg_w2, msg_w3, vote_w1, vote_w2,
                                  lstm_wih, lstm_whh,
                                  p_wm1, p_wm2, p_wm3, p_wv1, p_wv2, p_wcat);
    k_init<<<Bq, HH>>>(kv, nv, init_w1, init_b1, init_w2, init_b2,
                       init_w3, init_b3, p_init0);
    k_bcast<<<dim3(NNODE, Bq), HH>>>(p_init0, ln_g, ln_b, p_amh, p_c, p_eb);

    for (int it = 0; it < ITERS; it++) {
        k_mlpN<3, false><<<MROWS / 128, 256>>>(p_eb, p_wm1, p_wm2, p_wm3,
                                               msg_b1, msg_b2, msg_b3, p_mb);
        k_aggr_mma<<<dim3(NNODE / 128, Bq, KSPLIT), 256>>>(p_xb, p_mb, p_msgp);
        k_reduce_msg<<<MROWS * HH / (4 * 256), 256>>>(p_msgp, p_amh);
        k_gates_lstm<<<dim3(MROWS / 128, 4), 256>>>(p_amh, p_wcat, lstm_bih, lstm_bhh,
                                                    p_c, p_hb);
        k_hln<<<MROWS, HH>>>(p_hb, p_amh, p_eb, ln_g, ln_b);
    }

    k_mlpN<2, true><<<MROWS / 128, 256>>>(p_eb, p_wv1, p_wv2, p_wv2,
                                          vote_b1, vote_b2, vote_b2, p_t2b);
    k_vote<<<MROWS, HH>>>(p_t2b, vote_w3, vote_b3, mask, p_vote);
    k_final<<<Bq, 256>>>(p_vote, out);
}

// round 15
// speedup vs baseline: 1.3329x; 1.3329x over previous
#include <cuda_runtime.h>
#include <cuda_bf16.h>
#include <math.h>
#include <stdint.h>

#define Bq 4
#define NNODE 4096
#define HH 128
#define ITERS 8
#define EPS 1e-5f
#define MROWS (Bq * NNODE)   // 16384
#define KSPLIT 2
#define KSLICE (NNODE / KSPLIT)   // 2048

// smem paddings (bf16 elems per row)
#define XP 40    // 32 + 8
#define MP 136   // 128 + 8

// ---------------- scratch (device globals; no allocs allowed) ----------------
__device__ float g_init0[Bq * HH];
__device__ float g_c[(size_t)MROWS * HH];
__device__ float g_gates[(size_t)MROWS * 4 * HH];
__device__ float g_vote[MROWS];
__device__ float g_msgp[(size_t)KSPLIT * MROWS * HH];        // split-K partials (16 MB)
__device__ __nv_bfloat16 g_xb[(size_t)Bq * NNODE * NNODE];   // 128 MB
__device__ __nv_bfloat16 g_amh[(size_t)MROWS * 256];         // [msg | h]
__device__ __nv_bfloat16 g_eb[(size_t)MROWS * HH];           // embed
__device__ __nv_bfloat16 g_mb[(size_t)MROWS * HH];           // m (msg-MLP out)
__device__ __nv_bfloat16 g_t2b[(size_t)MROWS * HH];          // vote hidden
// transposed bf16 weights: wt[k][n]
__device__ __nv_bfloat16 g_wm1[HH * HH], g_wm2[HH * HH], g_wm3[HH * HH];
__device__ __nv_bfloat16 g_wv1[HH * HH], g_wv2[HH * HH];
__device__ __nv_bfloat16 g_wcat[256 * 512];                  // [Wih;Whh]^T

// ---------------- helpers ----------------
__device__ __forceinline__ float sigf(float x) { return 1.f / (1.f + expf(-x)); }
__device__ __forceinline__ uint32_t s2u(const void* p) {
    return (uint32_t)__cvta_generic_to_shared(p);
}
__device__ __forceinline__ void cpa16(void* dst, const void* src) {
    asm volatile("cp.async.cg.shared.global [%0], [%1], 16;\n" :: "r"(s2u(dst)), "l"(src));
}
#define CP_COMMIT() asm volatile("cp.async.commit_group;\n" ::: "memory")
#define CP_WAIT0()  asm volatile("cp.async.wait_group 0;\n" ::: "memory")
#define CP_WAIT1()  asm volatile("cp.async.wait_group 1;\n" ::: "memory")

__device__ __forceinline__ float blockSum128(float v) {
    __shared__ float sw[4];
    #pragma unroll
    for (int o = 16; o > 0; o >>= 1) v += __shfl_xor_sync(0xffffffffu, v, o);
    __syncthreads();
    if ((threadIdx.x & 31) == 0) sw[threadIdx.x >> 5] = v;
    __syncthreads();
    return sw[0] + sw[1] + sw[2] + sw[3];
}

__device__ __forceinline__ void ldmA(uint32_t* r, uint32_t addr) {
    asm volatile("ldmatrix.sync.aligned.m8n8.x4.shared.b16 {%0,%1,%2,%3}, [%4];\n"
                 : "=r"(r[0]), "=r"(r[1]), "=r"(r[2]), "=r"(r[3]) : "r"(addr));
}
__device__ __forceinline__ void ldmBT(uint32_t* r, uint32_t addr) {
    asm volatile("ldmatrix.sync.aligned.m8n8.x2.trans.shared.b16 {%0,%1}, [%2];\n"
                 : "=r"(r[0]), "=r"(r[1]) : "r"(addr));
}
__device__ __forceinline__ void mma16816(float* d, const uint32_t* a, const uint32_t* b) {
    asm volatile(
        "mma.sync.aligned.m16n8k16.row.col.f32.bf16.bf16.f32 "
        "{%0,%1,%2,%3}, {%4,%5,%6,%7}, {%8,%9}, {%0,%1,%2,%3};\n"
        : "+f"(d[0]), "+f"(d[1]), "+f"(d[2]), "+f"(d[3])
        : "r"(a[0]), "r"(a[1]), "r"(a[2]), "r"(a[3]), "r"(b[0]), "r"(b[1]));
}
__device__ __forceinline__ uint32_t packbf2(float x, float y) {
    __nv_bfloat162 p = __floats2bfloat162_rn(x, y);
    return *(uint32_t*)&p;
}

// ---------------- conversions (once per launch) ----------------
__global__ void k_cvt_x(const float* __restrict__ X, __nv_bfloat16* __restrict__ Xb) {
    size_t i = ((size_t)blockIdx.x * blockDim.x + threadIdx.x) * 4;
    float4 v = *(const float4*)&X[i];
    uint2 u;
    u.x = packbf2(v.x, v.y);
    u.y = packbf2(v.z, v.w);
    *(uint2*)&Xb[i] = u;
}
// all weight transposes in ONE kernel. jobs 0-4: HxH -> [k][n]; 5,6: wih/whh -> wcat
__global__ void k_cvtw(const float* s0, const float* s1, const float* s2,
                       const float* s3, const float* s4,
                       const float* wih, const float* whh,
                       __nv_bfloat16* d0, __nv_bfloat16* d1, __nv_bfloat16* d2,
                       __nv_bfloat16* d3, __nv_bfloat16* d4,
                       __nv_bfloat16* dcat) {
    int idx = blockIdx.x * 256 + threadIdx.x;
    int job = blockIdx.y;
    if (job < 5) {
        if (idx >= HH * HH) return;
        const float* s; __nv_bfloat16* d;
        switch (job) {
            case 0: s = s0; d = d0; break;
            case 1: s = s1; d = d1; break;
            case 2: s = s2; d = d2; break;
            case 3: s = s3; d = d3; break;
            default: s = s4; d = d4; break;
        }
        int n = idx >> 7, k = idx & 127;
        d[k * HH + n] = __float2bfloat16(s[idx]);
    } else {
        if (idx >= 512 * HH) return;
        const float* s = (job == 5) ? wih : whh;
        int koff = (job == 5) ? 0 : 128;
        int n = idx >> 7, k = idx & 127;
        dcat[(size_t)(k + koff) * 512 + n] = __float2bfloat16(s[idx]);
    }
}

// ---------------- tiny init MLP ----------------
__global__ void k_init(const float* __restrict__ kv, const float* __restrict__ nv,
                       const float* __restrict__ w1, const float* __restrict__ b1,
                       const float* __restrict__ w2, const float* __restrict__ b2,
                       const float* __restrict__ w3, const float* __restrict__ b3,
                       float* __restrict__ init0) {
    int b = blockIdx.x, j = threadIdx.x;
    __shared__ float s1[HH], s2[HH];
    float kk = kv[b], nn = nv[b];
    float v = fmaxf(w1[j * 2 + 0] * kk + w1[j * 2 + 1] * nn + b1[j], 0.f);
    s1[j] = v;
    __syncthreads();
    float acc = b2[j];
    #pragma unroll 8
    for (int t = 0; t < HH; t++) acc += w2[j * HH + t] * s1[t];
    s2[j] = fmaxf(acc, 0.f);
    __syncthreads();
    acc = b3[j];
    #pragma unroll 8
    for (int t = 0; t < HH; t++) acc += w3[j * HH + t] * s2[t];
    init0[b * HH + j] = acc;
}

// ---------------- broadcast: h(bf16)->amh, c=0, embed(bf16) ----------------
__global__ void k_bcast(const float* __restrict__ init0,
                        const float* __restrict__ lng, const float* __restrict__ lnb,
                        __nv_bfloat16* __restrict__ amh, float* __restrict__ c,
                        __nv_bfloat16* __restrict__ eb) {
    int b = blockIdx.y, i = blockIdx.x, j = threadIdx.x;
    float v = init0[b * HH + j];
    float mu = blockSum128(v) * (1.f / HH);
    float xc = v - mu;
    float var = blockSum128(xc * xc) * (1.f / HH);
    float e = xc * rsqrtf(var + EPS) * lng[j] + lnb[j];
    size_t row = (size_t)b * NNODE + i;
    amh[row * 256 + 128 + j] = __float2bfloat16(v);
    c[row * HH + j] = 0.f;
    eb[row * HH + j] = __float2bfloat16(e);
}

// ---------------- fused NL-layer MLP (bf16 mma), 128 rows/block ----------------
template <int NL, bool LAST_RELU>
__global__ void __launch_bounds__(256, 2) k_mlpN(const __nv_bfloat16* __restrict__ in,
                                                 const __nv_bfloat16* __restrict__ w0,
                                                 const __nv_bfloat16* __restrict__ w1,
                                                 const __nv_bfloat16* __restrict__ w2,
                                                 const float* __restrict__ b0,
                                                 const float* __restrict__ b1,
                                                 const float* __restrict__ b2,
                                                 __nv_bfloat16* __restrict__ out) {
    int m0 = blockIdx.x * 128;
    __shared__ __align__(16) __nv_bfloat16 Ab[128 * MP];
    __shared__ __align__(16) __nv_bfloat16 Wb[128 * MP];
    int tid = threadIdx.x;
    int lane = tid & 31, wid = tid >> 5;
    int warp_m = wid >> 2, warp_n = wid & 3;

    #pragma unroll
    for (int r = 0; r < 8; r++) {
        int idx = tid + r * 256;
        int row = idx >> 4, cs = idx & 15;
        cpa16(&Ab[row * MP + cs * 8], &in[(size_t)(m0 + row) * HH + cs * 8]);
    }
    CP_COMMIT();

    #pragma unroll
    for (int l = 0; l < NL; l++) {
        const __nv_bfloat16* wt = (l == 0) ? w0 : (l == 1) ? w1 : w2;
        const float* bias = (l == 0) ? b0 : (l == 1) ? b1 : b2;
        bool relu = (l < NL - 1) || LAST_RELU;
        #pragma unroll
        for (int r = 0; r < 8; r++) {
            int idx = tid + r * 256;
            int row = idx >> 4, cs = idx & 15;
            cpa16(&Wb[row * MP + cs * 8], &wt[(size_t)row * HH + cs * 8]);
        }
        CP_COMMIT();
        CP_WAIT0();
        __syncthreads();

        float acc[4][4][4];
        #pragma unroll
        for (int mi = 0; mi < 4; mi++)
            #pragma unroll
            for (int ni = 0; ni < 4; ni++)
                #pragma unroll
                for (int e = 0; e < 4; e++) acc[mi][ni][e] = 0.f;

        #pragma unroll
        for (int ks = 0; ks < 8; ks++) {
            int kk = ks * 16;
            uint32_t a[4][4], bb[4][2];
            #pragma unroll
            for (int mi = 0; mi < 4; mi++)
                ldmA(a[mi], s2u(&Ab[(warp_m * 64 + mi * 16 + (lane & 15)) * MP
                                    + kk + ((lane >> 4) << 3)]));
            #pragma unroll
            for (int ni = 0; ni < 4; ni++)
                ldmBT(bb[ni], s2u(&Wb[(kk + (lane & 15)) * MP + warp_n * 32 + ni * 8]));
            #pragma unroll
            for (int mi = 0; mi < 4; mi++)
                #pragma unroll
                for (int ni = 0; ni < 4; ni++) mma16816(acc[mi][ni], a[mi], bb[ni]);
        }
        __syncthreads();

        #pragma unroll
        for (int mi = 0; mi < 4; mi++)
            #pragma unroll
            for (int ni = 0; ni < 4; ni++) {
                int rl = warp_m * 64 + mi * 16 + (lane >> 2);
                int col = warp_n * 32 + ni * 8 + ((lane & 3) << 1);
                float bv0 = bias[col], bv1 = bias[col + 1];
                float v0 = acc[mi][ni][0] + bv0, v1 = acc[mi][ni][1] + bv1;
                float v2 = acc[mi][ni][2] + bv0, v3 = acc[mi][ni][3] + bv1;
                if (relu) {
                    v0 = fmaxf(v0, 0.f); v1 = fmaxf(v1, 0.f);
                    v2 = fmaxf(v2, 0.f); v3 = fmaxf(v3, 0.f);
                }
                uint32_t p0 = packbf2(v0, v1), p1 = packbf2(v2, v3);
                if (l < NL - 1) {
                    *(uint32_t*)&Ab[rl * MP + col] = p0;
                    *(uint32_t*)&Ab[(rl + 8) * MP + col] = p1;
                } else {
                    *(uint32_t*)&out[(size_t)(m0 + rl) * HH + col] = p0;
                    *(uint32_t*)&out[(size_t)(m0 + rl + 8) * HH + col] = p1;
                }
            }
        __syncthreads();
    }
}

// ---------------- tensor-core aggregation, split-K=2 ----------------
__device__ __forceinline__ void aggr_load(int tid, const __nv_bfloat16* __restrict__ A,
                                          const __nv_bfloat16* __restrict__ Bm,
                                          int m0, int k0,
                                          __nv_bfloat16* xs, __nv_bfloat16* ms) {
    #pragma unroll
    for (int r = 0; r < 2; r++) {
        int seg = tid + r * 256;
        int row = seg >> 2, cs = seg & 3;
        cpa16(&xs[row * XP + cs * 8], &A[(size_t)(m0 + row) * NNODE + k0 + cs * 8]);
    }
    #pragma unroll
    for (int r = 0; r < 2; r++) {
        int seg = tid + r * 256;
        int row = seg >> 4, cs = seg & 15;
        cpa16(&ms[row * MP + cs * 8], &Bm[(size_t)(k0 + row) * HH + cs * 8]);
    }
}

__global__ void __launch_bounds__(256, 2) k_aggr_mma(const __nv_bfloat16* __restrict__ Xb,
                                                     const __nv_bfloat16* __restrict__ Mb,
                                                     float* __restrict__ MSGP) {
    int b = blockIdx.y;
    int ks = blockIdx.z;
    const __nv_bfloat16* A  = Xb + (size_t)b * NNODE * NNODE;
    const __nv_bfloat16* Bm = Mb + (size_t)b * NNODE * HH;
    float* C = MSGP + ((size_t)ks * MROWS + (size_t)b * NNODE) * HH;
    int m0 = blockIdx.x * 128;
    int kbase = ks * KSLICE;

    __shared__ __align__(16) __nv_bfloat16 Xs[3][128 * XP];
    __shared__ __align__(16) __nv_bfloat16 Ms[3][32 * MP];

    int tid = threadIdx.x;
    int lane = tid & 31, wid = tid >> 5;
    int warp_m = wid >> 2, warp_n = wid & 3;

    float acc[4][4][4];
    #pragma unroll
    for (int mi = 0; mi < 4; mi++)
        #pragma unroll
        for (int ni = 0; ni < 4; ni++)
            #pragma unroll
            for (int e = 0; e < 4; e++) acc[mi][ni][e] = 0.f;

    aggr_load(tid, A, Bm, m0, kbase, Xs[0], Ms[0]);
    CP_COMMIT();
    aggr_load(tid, A, Bm, m0, kbase + 32, Xs[1], Ms[1]);
    CP_COMMIT();

    const int NC = KSLICE / 32;   // 64 chunks
    for (int kc = 0; kc < NC; kc++) {
        int cur = kc % 3;
        if (kc < NC - 1) { CP_WAIT1(); } else { CP_WAIT0(); }
        __syncthreads();
        if (kc + 2 < NC) {
            aggr_load(tid, A, Bm, m0, kbase + (kc + 2) * 32, Xs[(kc + 2) % 3], Ms[(kc + 2) % 3]);
            CP_COMMIT();
        }
        #pragma unroll
        for (int ksub = 0; ksub < 2; ksub++) {
            int kk = ksub * 16;
            uint32_t a[4][4], bb[4][2];
            #pragma unroll
            for (int mi = 0; mi < 4; mi++)
                ldmA(a[mi], s2u(&Xs[cur][(warp_m * 64 + mi * 16 + (lane & 15)) * XP
                                         + kk + ((lane >> 4) << 3)]));
            #pragma unroll
            for (int ni = 0; ni < 4; ni++)
                ldmBT(bb[ni], s2u(&Ms[cur][(kk + (lane & 15)) * MP + warp_n * 32 + ni * 8]));
            #pragma unroll
            for (int mi = 0; mi < 4; mi++)
                #pragma unroll
                for (int ni = 0; ni < 4; ni++) mma16816(acc[mi][ni], a[mi], bb[ni]);
        }
    }

    #pragma unroll
    for (int mi = 0; mi < 4; mi++)
        #pragma unroll
        for (int ni = 0; ni < 4; ni++) {
            int row = m0 + warp_m * 64 + mi * 16 + (lane >> 2);
            int col = warp_n * 32 + ni * 8 + ((lane & 3) << 1);
            float2 v0 = {acc[mi][ni][0], acc[mi][ni][1]};
            float2 v1 = {acc[mi][ni][2], acc[mi][ni][3]};
            *(float2*)&C[(size_t)row * HH + col] = v0;
            *(float2*)&C[(size_t)(row + 8) * HH + col] = v1;
        }
}

// ---------------- reduce split-K partials -> bf16 msg in amh ----------------
__global__ void k_reduce_msg(const float* __restrict__ MSGP,
                             __nv_bfloat16* __restrict__ AMH) {
    size_t i = ((size_t)blockIdx.x * 256 + threadIdx.x) * 4;
    float4 a = *(const float4*)&MSGP[i];
    float4 bphalf = *(const float4*)&MSGP[(size_t)MROWS * HH + i];
    size_t row = i >> 7;
    int col = (int)(i & 127);
    uint2 u;
    u.x = packbf2(a.x + bphalf.x, a.y + bphalf.y);
    u.y = packbf2(a.z + bphalf.z, a.w + bphalf.w);
    *(uint2*)&AMH[row * 256 + col] = u;
}

// ---------------- gates GEMM: [M,512] = amh[M,256] @ wcat[256,512], bf16 mma ----------------
__global__ void __launch_bounds__(256, 2) k_gates_mma(const __nv_bfloat16* __restrict__ AMH,
                                                      const __nv_bfloat16* __restrict__ Wc,
                                                      const float* __restrict__ bih,
                                                      const float* __restrict__ bhh,
                                                      float* __restrict__ G) {
    int m0 = blockIdx.x * 128;
    int n0 = blockIdx.y * 128;

    __shared__ __align__(16) __nv_bfloat16 Xs[3][128 * XP];
    __shared__ __align__(16) __nv_bfloat16 Ms[3][32 * MP];

    int tid = threadIdx.x;
    int lane = tid & 31, wid = tid >> 5;
    int warp_m = wid >> 2, warp_n = wid & 3;

    float acc[4][4][4];
    #pragma unroll
    for (int mi = 0; mi < 4; mi++)
        #pragma unroll
        for (int ni = 0; ni < 4; ni++)
            #pragma unroll
            for (int e = 0; e < 4; e++) acc[mi][ni][e] = 0.f;

    auto load = [&](int k0, __nv_bfloat16* xs, __nv_bfloat16* ms) {
        #pragma unroll
        for (int r = 0; r < 2; r++) {
            int seg = tid + r * 256;
            int row = seg >> 2, cs = seg & 3;
            cpa16(&xs[row * XP + cs * 8], &AMH[(size_t)(m0 + row) * 256 + k0 + cs * 8]);
        }
        #pragma unroll
        for (int r = 0; r < 2; r++) {
            int seg = tid + r * 256;
            int row = seg >> 4, cs = seg & 15;
            cpa16(&ms[row * MP + cs * 8], &Wc[(size_t)(k0 + row) * 512 + n0 + cs * 8]);
        }
    };

    load(0, Xs[0], Ms[0]);
    CP_COMMIT();
    load(32, Xs[1], Ms[1]);
    CP_COMMIT();

    const int NC = 256 / 32;
    for (int kc = 0; kc < NC; kc++) {
        int cur = kc % 3;
        if (kc < NC - 1) { CP_WAIT1(); } else { CP_WAIT0(); }
        __syncthreads();
        if (kc + 2 < NC) {
            load((kc + 2) * 32, Xs[(kc + 2) % 3], Ms[(kc + 2) % 3]);
            CP_COMMIT();
        }
        #pragma unroll
        for (int ks = 0; ks < 2; ks++) {
            int kk = ks * 16;
            uint32_t a[4][4], bb[4][2];
            #pragma unroll
            for (int mi = 0; mi < 4; mi++)
                ldmA(a[mi], s2u(&Xs[cur][(warp_m * 64 + mi * 16 + (lane & 15)) * XP
                                         + kk + ((lane >> 4) << 3)]));
            #pragma unroll
            for (int ni = 0; ni < 4; ni++)
                ldmBT(bb[ni], s2u(&Ms[cur][(kk + (lane & 15)) * MP + warp_n * 32 + ni * 8]));
            #pragma unroll
            for (int mi = 0; mi < 4; mi++)
                #pragma unroll
                for (int ni = 0; ni < 4; ni++) mma16816(acc[mi][ni], a[mi], bb[ni]);
        }
    }

    #pragma unroll
    for (int mi = 0; mi < 4; mi++)
        #pragma unroll
        for (int ni = 0; ni < 4; ni++) {
            int row = m0 + warp_m * 64 + mi * 16 + (lane >> 2);
            int cg = n0 + warp_n * 32 + ni * 8 + ((lane & 3) << 1);
            float b0 = bih[cg] + bhh[cg], b1 = bih[cg + 1] + bhh[cg + 1];
            float2 v0 = {acc[mi][ni][0] + b0, acc[mi][ni][1] + b1};
            float2 v1 = {acc[mi][ni][2] + b0, acc[mi][ni][3] + b1};
            *(float2*)&G[(size_t)row * 512 + cg] = v0;
            *(float2*)&G[(size_t)(row + 8) * 512 + cg] = v1;
        }
}

// ---------------- fused LSTM cell + LayerNorm ----------------
__global__ void k_lstm_ln(const float* __restrict__ gates, float* __restrict__ c,
                          __nv_bfloat16* __restrict__ amh, __nv_bfloat16* __restrict__ eb,
                          const float* __restrict__ lng, const float* __restrict__ lnb) {
    size_t row = blockIdx.x;
    int j = threadIdx.x;
    const float* gr = gates + row * 4 * HH;
    float gi = gr[j], gf = gr[HH + j], gg = gr[2 * HH + j], go = gr[3 * HH + j];
    size_t off = row * HH + j;
    float cc = sigf(gf) * c[off] + sigf(gi) * tanhf(gg);
    float hh = sigf(go) * tanhf(cc);
    c[off] = cc;
    amh[row * 256 + 128 + j] = __float2bfloat16(hh);
    float mu = blockSum128(hh) * (1.f / HH);
    float xc = hh - mu;
    float var = blockSum128(xc * xc) * (1.f / HH);
    eb[off] = __float2bfloat16(xc * rsqrtf(var + EPS) * lng[j] + lnb[j]);
}

// ---------------- vote dot + mask ----------------
__global__ void k_vote(const __nv_bfloat16* __restrict__ t2, const float* __restrict__ w3,
                       const float* __restrict__ b3, const float* __restrict__ mask,
                       float* __restrict__ vote) {
    size_t row = blockIdx.x;
    int j = threadIdx.x;
    float v = __bfloat162float(t2[row * HH + j]) * w3[j];
    float s = blockSum128(v);
    if (j == 0) vote[row] = (s + b3[0]) * mask[row];
}

// ---------------- final masked sum + sigmoid ----------------
__global__ void k_final(const float* __restrict__ vote, float* __restrict__ out) {
    __shared__ float sw[8];
    int b = blockIdx.x;
    float s = 0.f;
    for (int i = threadIdx.x; i < NNODE; i += blockDim.x) s += vote[(size_t)b * NNODE + i];
    #pragma unroll
    for (int o = 16; o > 0; o >>= 1) s += __shfl_xor_sync(0xffffffffu, s, o);
    if ((threadIdx.x & 31) == 0) sw[threadIdx.x >> 5] = s;
    __syncthreads();
    if (threadIdx.x == 0) {
        float t = 0.f;
        #pragma unroll
        for (int w = 0; w < 8; w++) t += sw[w];
        out[b] = 1.f / (1.f + expf(-t));
    }
}

// ---------------- launch ----------------
extern "C" void kernel_launch(void* const* d_in, const int* in_sizes, int n_in,
                              void* d_out, int out_size) {
    const float* x       = (const float*)d_in[0];
    const float* kv      = (const float*)d_in[1];
    const float* nv      = (const float*)d_in[2];
    const float* mask    = (const float*)d_in[3];
    const float* init_w1 = (const float*)d_in[4];
    const float* init_b1 = (const float*)d_in[5];
    const float* init_w2 = (const float*)d_in[6];
    const float* init_b2 = (const float*)d_in[7];
    const float* init_w3 = (const float*)d_in[8];
    const float* init_b3 = (const float*)d_in[9];
    const float* msg_w1  = (const float*)d_in[10];
    const float* msg_b1  = (const float*)d_in[11];
    const float* msg_w2  = (const float*)d_in[12];
    const float* msg_b2  = (const float*)d_in[13];
    const float* msg_w3  = (const float*)d_in[14];
    const float* msg_b3  = (const float*)d_in[15];
    const float* lstm_wih = (const float*)d_in[16];
    const float* lstm_whh = (const float*)d_in[17];
    const float* lstm_bih = (const float*)d_in[18];
    const float* lstm_bhh = (const float*)d_in[19];
    const float* ln_g    = (const float*)d_in[20];
    const float* ln_b    = (const float*)d_in[21];
    const float* vote_w1 = (const float*)d_in[22];
    const float* vote_b1 = (const float*)d_in[23];
    const float* vote_w2 = (const float*)d_in[24];
    const float* vote_b2 = (const float*)d_in[25];
    const float* vote_w3 = (const float*)d_in[26];
    const float* vote_b3 = (const float*)d_in[27];
    float* out = (float*)d_out;

    float *p_init0, *p_c, *p_gates, *p_vote, *p_msgp;
    __nv_bfloat16 *p_xb, *p_amh, *p_eb, *p_mb, *p_t2b;
    __nv_bfloat16 *p_wm1, *p_wm2, *p_wm3, *p_wv1, *p_wv2, *p_wcat;
    cudaGetSymbolAddress((void**)&p_init0, g_init0);
    cudaGetSymbolAddress((void**)&p_c, g_c);
    cudaGetSymbolAddress((void**)&p_gates, g_gates);
    cudaGetSymbolAddress((void**)&p_vote, g_vote);
    cudaGetSymbolAddress((void**)&p_msgp, g_msgp);
    cudaGetSymbolAddress((void**)&p_xb, g_xb);
    cudaGetSymbolAddress((void**)&p_amh, g_amh);
    cudaGetSymbolAddress((void**)&p_eb, g_eb);
    cudaGetSymbolAddress((void**)&p_mb, g_mb);
    cudaGetSymbolAddress((void**)&p_t2b, g_t2b);
    cudaGetSymbolAddress((void**)&p_wm1, g_wm1);
    cudaGetSymbolAddress((void**)&p_wm2, g_wm2);
    cudaGetSymbolAddress((void**)&p_wm3, g_wm3);
    cudaGetSymbolAddress((void**)&p_wv1, g_wv1);
    cudaGetSymbolAddress((void**)&p_wv2, g_wv2);
    cudaGetSymbolAddress((void**)&p_wcat, g_wcat);

    k_cvt_x<<<(size_t)Bq * NNODE * NNODE / 4 / 256, 256>>>(x, p_xb);
    k_cvtw<<<dim3(256, 7), 256>>>(msg_w1, msg_w2, msg_w3, vote_w1, vote_w2,
                                  lstm_wih, lstm_whh,
                                  p_wm1, p_wm2, p_wm3, p_wv1, p_wv2, p_wcat);
    k_init<<<Bq, HH>>>(kv, nv, init_w1, init_b1, init_w2, init_b2,
                       init_w3, init_b3, p_init0);
    k_bcast<<<dim3(NNODE, Bq), HH>>>(p_init0, ln_g, ln_b, p_amh, p_c, p_eb);

    for (int it = 0; it < ITERS; it++) {
        k_mlpN<3, false><<<MROWS / 128, 256>>>(p_eb, p_wm1, p_wm2, p_wm3,
                                               msg_b1, msg_b2, msg_b3, p_mb);
        k_aggr_mma<<<dim3(NNODE / 128, Bq, KSPLIT), 256>>>(p_xb, p_mb, p_msgp);
        k_reduce_msg<<<MROWS * HH / (4 * 256), 256>>>(p_msgp, p_amh);
        k_gates_mma<<<dim3(MROWS / 128, 4), 256>>>(p_amh, p_wcat, lstm_bih, lstm_bhh, p_gates);
        k_lstm_ln<<<MROWS, HH>>>(p_gates, p_c, p_amh, p_eb, ln_g, ln_b);
    }

    k_mlpN<2, true><<<MROWS / 128, 256>>>(p_eb, p_wv1, p_wv2, p_wv2,
                                          vote_b1, vote_b2, vote_b2, p_t2b);
    k_vote<<<MROWS, HH>>>(p_t2b, vote_w3, vote_b3, mask, p_vote);
    k_final<<<Bq, 256>>>(p_vote, out);
}